// round 1
// baseline (speedup 1.0000x reference)
#include <cuda_runtime.h>

#define QLEN 512
#define RLEN 1024
#define BSZ 8
#define NH 16
#define DH 64
#define DM 1024
#define MROWS (QLEN*BSZ)   /* 4096 */
#define RROWS (RLEN*BSZ)   /* 8192 */
#define ATTN_SCALE 0.125f  /* 1/sqrt(64) */

// ---------------- scratch (device globals: sanctioned, no runtime alloc) ----
__device__ float g_qh [MROWS*DM];
__device__ float g_qg [MROWS*DM];
__device__ float g_k  [MROWS*DM];
__device__ float g_v  [MROWS*DM];
__device__ float g_kr [RROWS*DM];
__device__ float g_avh[MROWS*DM];
__device__ float g_avg[MROWS*DM];
__device__ float g_oh [MROWS*DM];
__device__ float g_og [MROWS*DM];

// ---------------- generic tiled GEMM: C[M,1024] = A[M,1024] @ W[1024,1024] --
// 64x64 tile, BK=16, 256 threads, 4x4 microtile per thread.
__global__ __launch_bounds__(256) void gemm_nn_kernel(
    const float* __restrict__ A, const float* __restrict__ W,
    float* __restrict__ C)
{
    __shared__ float As[64][16];
    __shared__ float Bs[16][64];
    const int tid = threadIdx.x;
    const int tx = tid & 15, ty = tid >> 4;
    const int m0 = blockIdx.y * 64, n0 = blockIdx.x * 64;

    float acc[4][4];
#pragma unroll
    for (int i = 0; i < 4; i++)
#pragma unroll
        for (int j = 0; j < 4; j++) acc[i][j] = 0.f;

    const int ar = tid >> 2, ac4 = (tid & 3) * 4;   // A tile: 64 rows x 16
    const int br = tid >> 4, bc4 = (tid & 15) * 4;  // W tile: 16 rows x 64

    for (int k0 = 0; k0 < DM; k0 += 16) {
        float4 av = *(const float4*)&A[(size_t)(m0 + ar) * DM + k0 + ac4];
        float4 wv = *(const float4*)&W[(size_t)(k0 + br) * DM + n0 + bc4];
        *(float4*)&As[ar][ac4] = av;
        *(float4*)&Bs[br][bc4] = wv;
        __syncthreads();
#pragma unroll
        for (int k = 0; k < 16; k++) {
            float a0 = As[ty*4+0][k], a1 = As[ty*4+1][k];
            float a2 = As[ty*4+2][k], a3 = As[ty*4+3][k];
            float4 b = *(float4*)&Bs[k][tx*4];
            acc[0][0] += a0*b.x; acc[0][1] += a0*b.y; acc[0][2] += a0*b.z; acc[0][3] += a0*b.w;
            acc[1][0] += a1*b.x; acc[1][1] += a1*b.y; acc[1][2] += a1*b.z; acc[1][3] += a1*b.w;
            acc[2][0] += a2*b.x; acc[2][1] += a2*b.y; acc[2][2] += a2*b.z; acc[2][3] += a2*b.w;
            acc[3][0] += a3*b.x; acc[3][1] += a3*b.y; acc[3][2] += a3*b.z; acc[3][3] += a3*b.w;
        }
        __syncthreads();
    }
#pragma unroll
    for (int i = 0; i < 4; i++) {
        float4 o = make_float4(acc[i][0], acc[i][1], acc[i][2], acc[i][3]);
        *(float4*)&C[(size_t)(m0 + ty*4 + i) * DM + n0 + tx*4] = o;
    }
}

// -------- transposed GEMM: C[M,1024] = A[M,1024] @ W[1024,1024]^T -----------
// (contraction over W's second index: out[ib,h] = sum_nd av[ib,nd]*wo[h,nd])
__global__ __launch_bounds__(256) void gemm_tn_kernel(
    const float* __restrict__ A, const float* __restrict__ W,
    float* __restrict__ C)
{
    __shared__ float As[64][16];
    __shared__ float Bs[64][17];   // padded: strided reads in compute
    const int tid = threadIdx.x;
    const int tx = tid & 15, ty = tid >> 4;
    const int m0 = blockIdx.y * 64, n0 = blockIdx.x * 64;

    float acc[4][4];
#pragma unroll
    for (int i = 0; i < 4; i++)
#pragma unroll
        for (int j = 0; j < 4; j++) acc[i][j] = 0.f;

    const int ar = tid >> 2, ac4 = (tid & 3) * 4;

    for (int k0 = 0; k0 < DM; k0 += 16) {
        float4 av = *(const float4*)&A[(size_t)(m0 + ar) * DM + k0 + ac4];
        *(float4*)&As[ar][ac4] = av;
        float4 wv = *(const float4*)&W[(size_t)(n0 + ar) * DM + k0 + ac4];
        Bs[ar][ac4+0] = wv.x; Bs[ar][ac4+1] = wv.y;
        Bs[ar][ac4+2] = wv.z; Bs[ar][ac4+3] = wv.w;
        __syncthreads();
#pragma unroll
        for (int k = 0; k < 16; k++) {
            float a0 = As[ty*4+0][k], a1 = As[ty*4+1][k];
            float a2 = As[ty*4+2][k], a3 = As[ty*4+3][k];
            float b0 = Bs[tx*4+0][k], b1 = Bs[tx*4+1][k];
            float b2 = Bs[tx*4+2][k], b3 = Bs[tx*4+3][k];
            acc[0][0] += a0*b0; acc[0][1] += a0*b1; acc[0][2] += a0*b2; acc[0][3] += a0*b3;
            acc[1][0] += a1*b0; acc[1][1] += a1*b1; acc[1][2] += a1*b2; acc[1][3] += a1*b3;
            acc[2][0] += a2*b0; acc[2][1] += a2*b1; acc[2][2] += a2*b2; acc[2][3] += a2*b3;
            acc[3][0] += a3*b0; acc[3][1] += a3*b1; acc[3][2] += a3*b2; acc[3][3] += a3*b3;
        }
        __syncthreads();
    }
#pragma unroll
    for (int i = 0; i < 4; i++) {
        float4 o = make_float4(acc[i][0], acc[i][1], acc[i][2], acc[i][3]);
        *(float4*)&C[(size_t)(m0 + ty*4 + i) * DM + n0 + tx*4] = o;
    }
}

// ---------------- fused attention --------------------------------------------
// Block: 16 i-rows x full 512 j, one (b,n,stream).
// rel_shift identity: bd_shifted[i,j] = dot(q+rr, k_r[512 + j - i]).
// grid: (QLEN/16, BSZ*NH [n fastest], 2 streams)
#define SM_S      0                     // 16*512 scores
#define SM_QAC    (16*512)              // 16*64
#define SM_QBD    (SM_QAC + 16*64)      // 16*64
#define SM_EF     (SM_QBD + 16*64)      // 16*2
#define SM_ROWSUM (SM_EF + 32)          // 16
#define SM_KTV    (SM_ROWSUM + 16)      // 64*68 kT (stride 68) / v (stride 64)
#define SM_KR     (SM_KTV + 64*68)      // 64*80 k_r window transposed
#define ATTN_SMEM_FLOATS (SM_KR + 64*80)
#define ATTN_SMEM_BYTES  (ATTN_SMEM_FLOATS * 4)

__global__ __launch_bounds__(256) void attn_kernel(
    const float* __restrict__ mask_h, const float* __restrict__ mask_g,
    const float* __restrict__ seg,
    const float* __restrict__ rwb, const float* __restrict__ rrb,
    const float* __restrict__ rsb, const float* __restrict__ se)
{
    extern __shared__ float sm[];
    float* Ssm    = sm + SM_S;
    float* qac    = sm + SM_QAC;
    float* qbd    = sm + SM_QBD;
    float* efs    = sm + SM_EF;
    float* rowsum = sm + SM_ROWSUM;
    float* ktv    = sm + SM_KTV;
    float* krT    = sm + SM_KR;

    const int tid = threadIdx.x;
    const int tx = tid & 15, ty = tid >> 4;
    const int i0 = blockIdx.x * 16;
    const int b  = blockIdx.y >> 4;
    const int n  = blockIdx.y & 15;
    const int st = blockIdx.z;

    const float* q    = st ? g_qg : g_qh;
    const float* mask = st ? mask_g : mask_h;
    float*       av   = st ? g_avg : g_avh;

    // q tile + biases (1 float4 / thread: 16 rows x 16 groups)
    {
        const int il = tid >> 4, d4 = (tid & 15) * 4;
        float4 qv = *(const float4*)&q[((size_t)(i0+il)*BSZ + b)*DM + n*DH + d4];
        float4 rw = *(const float4*)&rwb[n*DH + d4];
        float4 rr = *(const float4*)&rrb[n*DH + d4];
        *(float4*)&qac[il*DH + d4] = make_float4(qv.x+rw.x, qv.y+rw.y, qv.z+rw.z, qv.w+rw.w);
        *(float4*)&qbd[il*DH + d4] = make_float4(qv.x+rr.x, qv.y+rr.y, qv.z+rr.z, qv.w+rr.w);
    }
    // ef[i][s] = dot(q[i]+r_s_bias, seg_embed[s,n,:])
    if (tid < 32) {
        const int il = tid >> 1, s = tid & 1;
        const float* qrow = &q[((size_t)(i0+il)*BSZ + b)*DM + n*DH];
        const float* srow = &se[(s*NH + n)*DH];
        const float* rs   = &rsb[n*DH];
        float acc = 0.f;
#pragma unroll 8
        for (int d = 0; d < DH; d++) acc += (qrow[d] + rs[d]) * srow[d];
        efs[il*2 + s] = acc;
    }

    // ---- phase 1: scores ----
    for (int j0 = 0; j0 < QLEN; j0 += 64) {
        __syncthreads();   // also covers q/ef publication on first iter
        // k tile transposed: ktv[d][j], stride 68
        for (int t = tid; t < 64*16; t += 256) {
            int jl = t >> 4, d4 = (t & 15) * 4;
            float4 kv = *(const float4*)&g_k[((size_t)(j0+jl)*BSZ + b)*DM + n*DH + d4];
            ktv[(d4+0)*68 + jl] = kv.x; ktv[(d4+1)*68 + jl] = kv.y;
            ktv[(d4+2)*68 + jl] = kv.z; ktv[(d4+3)*68 + jl] = kv.w;
        }
        // k_r window: rows base..base+78 (all in [0,1024)), transposed, stride 80
        const int base = 512 + j0 - i0 - 15;
        for (int t = tid; t < 79*16; t += 256) {
            int w = t >> 4, d4 = (t & 15) * 4;
            float4 kv = *(const float4*)&g_kr[((size_t)(base+w)*BSZ + b)*DM + n*DH + d4];
            krT[(d4+0)*80 + w] = kv.x; krT[(d4+1)*80 + w] = kv.y;
            krT[(d4+2)*80 + w] = kv.z; krT[(d4+3)*80 + w] = kv.w;
        }
        __syncthreads();

        float s0=0.f, s1=0.f, s2=0.f, s3=0.f;
        const int wb = tx*4 + 15 - ty;   // k_r window index for jj=0
#pragma unroll 4
        for (int d = 0; d < DH; d++) {
            float qa = qac[ty*DH + d];
            float qb = qbd[ty*DH + d];
            float4 k4 = *(float4*)&ktv[d*68 + tx*4];
            const float* kr = &krT[d*80 + wb];
            s0 += qa*k4.x + qb*kr[0];
            s1 += qa*k4.y + qb*kr[1];
            s2 += qa*k4.z + qb*kr[2];
            s3 += qa*k4.w + qb*kr[3];
        }
        float e0 = efs[ty*2+0], e1 = efs[ty*2+1];
        float sv[4] = {s0, s1, s2, s3};
#pragma unroll
        for (int jj = 0; jj < 4; jj++) {
            int jg = j0 + tx*4 + jj;
            size_t ij = ((size_t)(i0+ty)*QLEN + jg)*BSZ + b;
            float2 sg = *(const float2*)&seg[ij*2];
            float mk = mask[ij*NH + n];
            Ssm[ty*512 + jg] = (sv[jj] + sg.x*e0 + sg.y*e1) * ATTN_SCALE - 1e30f*mk;
        }
    }
    __syncthreads();

    // ---- phase 2: softmax (unnormalized exp in smem, row sums kept) ----
    {
        const int lane = tid & 31, w = tid >> 5;
        const int il = w*2 + (lane >> 4);
        const int l16 = lane & 15;
        float m = -3.0e38f;
        for (int j = l16; j < 512; j += 16) m = fmaxf(m, Ssm[il*512 + j]);
#pragma unroll
        for (int o = 8; o >= 1; o >>= 1) m = fmaxf(m, __shfl_xor_sync(0xffffffffu, m, o));
        float ssum = 0.f;
        for (int j = l16; j < 512; j += 16) {
            float p = __expf(Ssm[il*512 + j] - m);
            Ssm[il*512 + j] = p;
            ssum += p;
        }
#pragma unroll
        for (int o = 8; o >= 1; o >>= 1) ssum += __shfl_xor_sync(0xffffffffu, ssum, o);
        if (l16 == 0) rowsum[il] = ssum;
    }
    __syncthreads();

    // ---- phase 3: P @ V ----
    float a0=0.f, a1=0.f, a2=0.f, a3=0.f;
    for (int j0 = 0; j0 < QLEN; j0 += 64) {
        for (int t = tid; t < 64*16; t += 256) {
            int jl = t >> 4, d4 = (t & 15) * 4;
            *(float4*)&ktv[jl*64 + d4] =
                *(const float4*)&g_v[((size_t)(j0+jl)*BSZ + b)*DM + n*DH + d4];
        }
        __syncthreads();
#pragma unroll 8
        for (int j = 0; j < 64; j++) {
            float p = Ssm[ty*512 + j0 + j];
            float4 v4 = *(float4*)&ktv[j*64 + tx*4];
            a0 += p*v4.x; a1 += p*v4.y; a2 += p*v4.z; a3 += p*v4.w;
        }
        __syncthreads();
    }
    float inv = 1.0f / rowsum[ty];
    *(float4*)&av[((size_t)(i0+ty)*BSZ + b)*DM + n*DH + tx*4] =
        make_float4(a0*inv, a1*inv, a2*inv, a3*inv);
}

// ---------------- residual + LayerNorm --------------------------------------
__global__ __launch_bounds__(256) void ln_kernel(
    const float* __restrict__ resid_h, const float* __restrict__ resid_g,
    const float* __restrict__ gamma, const float* __restrict__ beta,
    float* __restrict__ out)
{
    __shared__ float red[8];
    __shared__ float bval;
    const int row = blockIdx.x;
    const int st  = blockIdx.y;
    const float* proj  = st ? g_og : g_oh;
    const float* resid = st ? resid_g : resid_h;
    float* o = out + (size_t)st * MROWS * DM + (size_t)row * DM;
    const int tid = threadIdx.x;
    const int lane = tid & 31, w = tid >> 5;

    float4 pv = *(const float4*)&proj [(size_t)row*DM + tid*4];
    float4 rv = *(const float4*)&resid[(size_t)row*DM + tid*4];
    float v0 = pv.x+rv.x, v1 = pv.y+rv.y, v2 = pv.z+rv.z, v3 = pv.w+rv.w;

    float s = v0+v1+v2+v3;
#pragma unroll
    for (int off = 16; off >= 1; off >>= 1) s += __shfl_xor_sync(0xffffffffu, s, off);
    if (lane == 0) red[w] = s;
    __syncthreads();
    if (tid == 0) {
        float t = 0.f;
#pragma unroll
        for (int i = 0; i < 8; i++) t += red[i];
        bval = t * (1.0f / DM);
    }
    __syncthreads();
    const float mu = bval;
    float d0 = v0-mu, d1 = v1-mu, d2 = v2-mu, d3 = v3-mu;
    float sq = d0*d0 + d1*d1 + d2*d2 + d3*d3;
#pragma unroll
    for (int off = 16; off >= 1; off >>= 1) sq += __shfl_xor_sync(0xffffffffu, sq, off);
    __syncthreads();
    if (lane == 0) red[w] = sq;
    __syncthreads();
    if (tid == 0) {
        float t = 0.f;
#pragma unroll
        for (int i = 0; i < 8; i++) t += red[i];
        bval = rsqrtf(t * (1.0f / DM) + 1e-12f);
    }
    __syncthreads();
    const float rstd = bval;
    float4 gm = *(const float4*)&gamma[tid*4];
    float4 bt = *(const float4*)&beta[tid*4];
    float4 ov = make_float4(d0*rstd*gm.x + bt.x, d1*rstd*gm.y + bt.y,
                            d2*rstd*gm.z + bt.z, d3*rstd*gm.w + bt.w);
    *(float4*)&o[tid*4] = ov;
}

// ---------------- launch ------------------------------------------------------
extern "C" void kernel_launch(void* const* d_in, const int* in_sizes, int n_in,
                              void* d_out, int out_size)
{
    const float* h    = (const float*)d_in[0];
    const float* g    = (const float*)d_in[1];
    const float* r    = (const float*)d_in[2];
    const float* amh  = (const float*)d_in[3];
    const float* amg  = (const float*)d_in[4];
    const float* seg  = (const float*)d_in[5];
    const float* wq   = (const float*)d_in[6];
    const float* wk   = (const float*)d_in[7];
    const float* wv   = (const float*)d_in[8];
    const float* wo   = (const float*)d_in[9];
    const float* wr   = (const float*)d_in[10];
    const float* rwb  = (const float*)d_in[11];
    const float* rrb  = (const float*)d_in[12];
    const float* rsb  = (const float*)d_in[13];
    const float* se   = (const float*)d_in[14];
    const float* gam  = (const float*)d_in[15];
    const float* bet  = (const float*)d_in[16];
    float* out = (float*)d_out;

    float *qh, *qg, *k, *v, *kr, *avh, *avg, *oh, *og;
    cudaGetSymbolAddress((void**)&qh,  g_qh);
    cudaGetSymbolAddress((void**)&qg,  g_qg);
    cudaGetSymbolAddress((void**)&k,   g_k);
    cudaGetSymbolAddress((void**)&v,   g_v);
    cudaGetSymbolAddress((void**)&kr,  g_kr);
    cudaGetSymbolAddress((void**)&avh, g_avh);
    cudaGetSymbolAddress((void**)&avg, g_avg);
    cudaGetSymbolAddress((void**)&oh,  g_oh);
    cudaGetSymbolAddress((void**)&og,  g_og);

    cudaFuncSetAttribute(attn_kernel,
                         cudaFuncAttributeMaxDynamicSharedMemorySize,
                         ATTN_SMEM_BYTES);

    dim3 blk(256);
    // projections
    gemm_nn_kernel<<<dim3(16,  64), blk>>>(h, wq, qh);
    gemm_nn_kernel<<<dim3(16,  64), blk>>>(g, wq, qg);
    gemm_nn_kernel<<<dim3(16,  64), blk>>>(h, wk, k);
    gemm_nn_kernel<<<dim3(16,  64), blk>>>(h, wv, v);
    gemm_nn_kernel<<<dim3(16, 128), blk>>>(r, wr, kr);
    // fused relative attention (both streams)
    attn_kernel<<<dim3(QLEN/16, BSZ*NH, 2), blk, ATTN_SMEM_BYTES>>>(
        amh, amg, seg, rwb, rrb, rsb, se);
    // output projection (W transposed contraction)
    gemm_tn_kernel<<<dim3(16, 64), blk>>>(avh, wo, oh);
    gemm_tn_kernel<<<dim3(16, 64), blk>>>(avg, wo, og);
    // residual + layernorm
    ln_kernel<<<dim3(MROWS, 2), blk>>>(h, g, gam, bet, out);
}

// round 3
// speedup vs baseline: 2.8496x; 2.8496x over previous
#include <cuda_runtime.h>
#include <cstdint>

#define QLEN 512
#define BSZ 8
#define NH 16
#define DH 64
#define DM 1024
#define MROWS (QLEN*BSZ)   /* 4096 */
#define RROWS (1024*BSZ)   /* 8192 */

// ---------------- scratch (device globals) ----------------------------------
__device__ float g_qh [MROWS*DM];
__device__ float g_qg [MROWS*DM];
__device__ float g_k  [MROWS*DM];
__device__ float g_v  [MROWS*DM];
__device__ float g_kr [RROWS*DM];
__device__ float g_avh[MROWS*DM];
__device__ float g_avg[MROWS*DM];
__device__ float g_oh [MROWS*DM];
__device__ float g_og [MROWS*DM];

// ---------------- tf32 helpers ----------------------------------------------
__device__ __forceinline__ unsigned f2tf(float x) {
    unsigned r;
    asm("cvt.rna.tf32.f32 %0, %1;" : "=r"(r) : "f"(x));
    return r;
}
__device__ __forceinline__ void mma8(float &c0, float &c1, float &c2, float &c3,
                                     const unsigned a[4], unsigned b0, unsigned b1)
{
    asm volatile("mma.sync.aligned.m16n8k8.row.col.f32.tf32.tf32.f32 "
        "{%0,%1,%2,%3},{%4,%5,%6,%7},{%8,%9},{%0,%1,%2,%3};"
        : "+f"(c0), "+f"(c1), "+f"(c2), "+f"(c3)
        : "r"(a[0]), "r"(a[1]), "r"(a[2]), "r"(a[3]), "r"(b0), "r"(b1));
}
__device__ __forceinline__ uint4 tf4(float4 v, float4 w) {
    return make_uint4(f2tf(v.x + w.x), f2tf(v.y + w.y), f2tf(v.z + w.z), f2tf(v.w + w.w));
}
__device__ __forceinline__ uint4 tf4(float4 v) {
    return make_uint4(f2tf(v.x), f2tf(v.y), f2tf(v.z), f2tf(v.w));
}

// ---------------- TF32 GEMM nn: C[M,1024] = A[M,1024] @ W[1024,1024] --------
__global__ __launch_bounds__(256) void gemm_nn_tf32(
    const float* __restrict__ A, const float* __restrict__ W, float* __restrict__ C)
{
    __shared__ unsigned As[128*36];   // [m][k] stride 36 (4g+tig distinct mod32)
    __shared__ unsigned Bs[32*136];   // [k][n] stride 136 (8tig+g distinct mod32)
    const int tid = threadIdx.x;
    const int lane = tid & 31, warp = tid >> 5;
    const int g = lane >> 2, tig = lane & 3;
    const int wm = (warp >> 2) * 64, wn = (warp & 3) * 32;
    const int m0 = blockIdx.y * 128, n0 = blockIdx.x * 128;

    float acc[4][4][4];
#pragma unroll
    for (int mt = 0; mt < 4; mt++)
#pragma unroll
        for (int nt = 0; nt < 4; nt++)
#pragma unroll
            for (int i = 0; i < 4; i++) acc[mt][nt][i] = 0.f;

    const int ar = tid >> 3, ac4 = (tid & 7) * 4;
    const int br = tid >> 5, bc4 = (tid & 31) * 4;

    for (int k0 = 0; k0 < DM; k0 += 32) {
#pragma unroll
        for (int p = 0; p < 4; p++) {
            float4 v = *(const float4*)&A[(size_t)(m0 + ar + p*32)*DM + k0 + ac4];
            *(uint4*)&As[(ar + p*32)*36 + ac4] = tf4(v);
        }
#pragma unroll
        for (int p = 0; p < 4; p++) {
            float4 v = *(const float4*)&W[(size_t)(k0 + br + p*8)*DM + n0 + bc4];
            *(uint4*)&Bs[(br + p*8)*136 + bc4] = tf4(v);
        }
        __syncthreads();
#pragma unroll
        for (int ks = 0; ks < 4; ks++) {
            unsigned af[4][4], bf[4][2];
#pragma unroll
            for (int mt = 0; mt < 4; mt++) {
                int r = (wm + mt*16 + g)*36 + ks*8 + tig;
                af[mt][0] = As[r];       af[mt][1] = As[r + 8*36];
                af[mt][2] = As[r + 4];   af[mt][3] = As[r + 8*36 + 4];
            }
#pragma unroll
            for (int nt = 0; nt < 4; nt++) {
                int r = (ks*8 + tig)*136 + wn + nt*8 + g;
                bf[nt][0] = Bs[r];  bf[nt][1] = Bs[r + 4*136];
            }
#pragma unroll
            for (int mt = 0; mt < 4; mt++)
#pragma unroll
                for (int nt = 0; nt < 4; nt++)
                    mma8(acc[mt][nt][0], acc[mt][nt][1], acc[mt][nt][2], acc[mt][nt][3],
                         af[mt], bf[nt][0], bf[nt][1]);
        }
        __syncthreads();
    }
#pragma unroll
    for (int mt = 0; mt < 4; mt++) {
        int row = m0 + wm + mt*16 + g;
#pragma unroll
        for (int nt = 0; nt < 4; nt++) {
            int col = n0 + wn + nt*8 + 2*tig;
            *(float2*)&C[(size_t)row*DM + col]     = make_float2(acc[mt][nt][0], acc[mt][nt][1]);
            *(float2*)&C[(size_t)(row+8)*DM + col] = make_float2(acc[mt][nt][2], acc[mt][nt][3]);
        }
    }
}

// ---------------- TF32 GEMM tn: C[M,1024] = A[M,1024] @ W[1024,1024]^T ------
__global__ __launch_bounds__(256) void gemm_tn_tf32(
    const float* __restrict__ A, const float* __restrict__ W, float* __restrict__ C)
{
    __shared__ unsigned As[128*36];   // [m][k]
    __shared__ unsigned Bs[128*36];   // [n][k]
    const int tid = threadIdx.x;
    const int lane = tid & 31, warp = tid >> 5;
    const int g = lane >> 2, tig = lane & 3;
    const int wm = (warp >> 2) * 64, wn = (warp & 3) * 32;
    const int m0 = blockIdx.y * 128, n0 = blockIdx.x * 128;

    float acc[4][4][4];
#pragma unroll
    for (int mt = 0; mt < 4; mt++)
#pragma unroll
        for (int nt = 0; nt < 4; nt++)
#pragma unroll
            for (int i = 0; i < 4; i++) acc[mt][nt][i] = 0.f;

    const int ar = tid >> 3, ac4 = (tid & 7) * 4;

    for (int k0 = 0; k0 < DM; k0 += 32) {
#pragma unroll
        for (int p = 0; p < 4; p++) {
            float4 v = *(const float4*)&A[(size_t)(m0 + ar + p*32)*DM + k0 + ac4];
            *(uint4*)&As[(ar + p*32)*36 + ac4] = tf4(v);
            float4 w = *(const float4*)&W[(size_t)(n0 + ar + p*32)*DM + k0 + ac4];
            *(uint4*)&Bs[(ar + p*32)*36 + ac4] = tf4(w);
        }
        __syncthreads();
#pragma unroll
        for (int ks = 0; ks < 4; ks++) {
            unsigned af[4][4], bf[4][2];
#pragma unroll
            for (int mt = 0; mt < 4; mt++) {
                int r = (wm + mt*16 + g)*36 + ks*8 + tig;
                af[mt][0] = As[r];       af[mt][1] = As[r + 8*36];
                af[mt][2] = As[r + 4];   af[mt][3] = As[r + 8*36 + 4];
            }
#pragma unroll
            for (int nt = 0; nt < 4; nt++) {
                int r = (wn + nt*8 + g)*36 + ks*8 + tig;
                bf[nt][0] = Bs[r];  bf[nt][1] = Bs[r + 4];
            }
#pragma unroll
            for (int mt = 0; mt < 4; mt++)
#pragma unroll
                for (int nt = 0; nt < 4; nt++)
                    mma8(acc[mt][nt][0], acc[mt][nt][1], acc[mt][nt][2], acc[mt][nt][3],
                         af[mt], bf[nt][0], bf[nt][1]);
        }
        __syncthreads();
    }
#pragma unroll
    for (int mt = 0; mt < 4; mt++) {
        int row = m0 + wm + mt*16 + g;
#pragma unroll
        for (int nt = 0; nt < 4; nt++) {
            int col = n0 + wn + nt*8 + 2*tig;
            *(float2*)&C[(size_t)row*DM + col]     = make_float2(acc[mt][nt][0], acc[mt][nt][1]);
            *(float2*)&C[(size_t)(row+8)*DM + col] = make_float2(acc[mt][nt][2], acc[mt][nt][3]);
        }
    }
}

// ---------------- fused tensor-core attention --------------------------------
// smem layout (32-bit words)
#define SOFF_S   0                  // scores 16 x 512, row stride 516
#define SOFF_SAC 8256               // ac chunk 16 x 64, stride 68
#define SOFF_W   9344               // bd window 16 x 80, stride 84
#define SOFF_EF  10688              // 16 x 2
#define SOFF_RS  10720              // 16 rowsums
#define SOFF_K   10736              // K chunk 64 x 64 (stride 68); Q staging (2 x 16 x 68)
#define SOFF_KR  15088              // kr window 80 x 64 (stride 68); V chunk 64 x 64 (stride 72)
#define ATTN_WORDS 20528
#define ATTN_BYTES (ATTN_WORDS*4)

__global__ __launch_bounds__(256) void attn_tc_kernel(
    const float* __restrict__ mask_h, const float* __restrict__ mask_g,
    const float* __restrict__ seg,
    const float* __restrict__ rwb, const float* __restrict__ rrb,
    const float* __restrict__ rsb, const float* __restrict__ se)
{
    extern __shared__ float sm[];
    unsigned* smU = (unsigned*)sm;
    const int tid  = threadIdx.x;
    const int lane = tid & 31, warp = tid >> 5;
    const int g = lane >> 2, tig = lane & 3;
    const int i0 = blockIdx.x * 16;
    const int b  = blockIdx.y >> 4;
    const int n  = blockIdx.y & 15;
    const int st = blockIdx.z;

    const float* q    = st ? g_qg : g_qh;
    const float* mask = st ? mask_g : mask_h;
    float*       av   = st ? g_avg : g_avh;

    // ---- stage Q(+rw), Q(+rr) as tf32 ----
    {
        const int il = tid >> 4, d4 = (tid & 15) * 4;
        float4 qv = *(const float4*)&q[((size_t)(i0+il)*BSZ + b)*DM + n*DH + d4];
        float4 rw = *(const float4*)&rwb[n*DH + d4];
        float4 rr = *(const float4*)&rrb[n*DH + d4];
        *(uint4*)&smU[SOFF_K + il*68 + d4]        = tf4(qv, rw);
        *(uint4*)&smU[SOFF_K + 1088 + il*68 + d4] = tf4(qv, rr);
    }
    // ef[i][s] = dot(q[i]+r_s_bias, seg_embed[s,n,:])  (fp32)
    if (tid < 32) {
        const int il = tid >> 1, s = tid & 1;
        const float* qrow = &q[((size_t)(i0+il)*BSZ + b)*DM + n*DH];
        const float* srow = &se[(s*NH + n)*DH];
        const float* rs   = &rsb[n*DH];
        float acc = 0.f;
#pragma unroll 8
        for (int d = 0; d < DH; d++) acc += (qrow[d] + rs[d]) * srow[d];
        sm[SOFF_EF + il*2 + s] = acc;
    }
    __syncthreads();

    // ---- hoist Q fragments into registers (reused for all 8 chunks) ----
    unsigned qa[8][4], qb[8][4];
#pragma unroll
    for (int ks = 0; ks < 8; ks++) {
        int r = SOFF_K + g*68 + ks*8 + tig;
        qa[ks][0] = smU[r];       qa[ks][1] = smU[r + 8*68];
        qa[ks][2] = smU[r + 4];   qa[ks][3] = smU[r + 8*68 + 4];
        r += 1088;
        qb[ks][0] = smU[r];       qb[ks][1] = smU[r + 8*68];
        qb[ks][2] = smU[r + 4];   qb[ks][3] = smU[r + 8*68 + 4];
    }

    // ---- phase 1: scores ----
    for (int j0 = 0; j0 < QLEN; j0 += 64) {
        __syncthreads();   // Q-frag loads / prev mma reads / prev assemble done
        {
            const int jl = tid >> 4, d4 = (tid & 15) * 4;
#pragma unroll
            for (int p = 0; p < 4; p++) {
                int j = jl + p*16;
                float4 kv = *(const float4*)&g_k[((size_t)(j0+j)*BSZ + b)*DM + n*DH + d4];
                *(uint4*)&smU[SOFF_K + j*68 + d4] = tf4(kv);
            }
            const int base = 512 + j0 - i0 - 15;
#pragma unroll
            for (int p = 0; p < 5; p++) {
                int w = jl + p*16;
                int r = base + w; if (r > 1023) r = 1023;   // row 79 unused
                float4 kv = *(const float4*)&g_kr[((size_t)r*BSZ + b)*DM + n*DH + d4];
                *(uint4*)&smU[SOFF_KR + w*68 + d4] = tf4(kv);
            }
        }
        __syncthreads();
        // ac tile (warp owns j cols [8w,8w+8))
        {
            float c0=0.f, c1=0.f, c2=0.f, c3=0.f;
#pragma unroll
            for (int ks = 0; ks < 8; ks++) {
                int r = SOFF_K + (warp*8 + g)*68 + ks*8 + tig;
                mma8(c0, c1, c2, c3, qa[ks], smU[r], smU[r + 4]);
            }
            *(float2*)&sm[SOFF_SAC + g*68 + warp*8 + 2*tig]       = make_float2(c0, c1);
            *(float2*)&sm[SOFF_SAC + (g+8)*68 + warp*8 + 2*tig]   = make_float2(c2, c3);
        }
        // bd window tiles (10 tiles over 8 warps)
        for (int bt = warp; bt < 10; bt += 8) {
            float c0=0.f, c1=0.f, c2=0.f, c3=0.f;
#pragma unroll
            for (int ks = 0; ks < 8; ks++) {
                int r = SOFF_KR + (bt*8 + g)*68 + ks*8 + tig;
                mma8(c0, c1, c2, c3, qb[ks], smU[r], smU[r + 4]);
            }
            *(float2*)&sm[SOFF_W + g*84 + bt*8 + 2*tig]     = make_float2(c0, c1);
            *(float2*)&sm[SOFF_W + (g+8)*84 + bt*8 + 2*tig] = make_float2(c2, c3);
        }
        __syncthreads();
        // assemble: S = (ac + bd_shift + seg*ef)*scale - 1e30*mask
        {
            const int il = tid >> 4, jj0 = (tid & 15) * 4;
            float e0 = sm[SOFF_EF + il*2], e1 = sm[SOFF_EF + il*2 + 1];
#pragma unroll
            for (int u = 0; u < 4; u++) {
                int jj = jj0 + u, jg = j0 + jj;
                size_t ij = ((size_t)(i0+il)*QLEN + jg)*BSZ + b;
                float2 sg = *(const float2*)&seg[ij*2];
                float  mk = mask[ij*NH + n];
                float  v  = sm[SOFF_SAC + il*68 + jj] + sm[SOFF_W + il*84 + jj + 15 - il];
                sm[SOFF_S + il*516 + jg] = (v + sg.x*e0 + sg.y*e1) * 0.125f - 1e30f*mk;
            }
        }
    }
    __syncthreads();

    // ---- phase 2: softmax (unnormalized exp; rowsums) ----
    {
        const int il  = warp*2 + (lane >> 4);
        const int l16 = lane & 15;
        float m = -3.0e38f;
        for (int j = l16; j < 512; j += 16) m = fmaxf(m, sm[SOFF_S + il*516 + j]);
#pragma unroll
        for (int o = 8; o >= 1; o >>= 1) m = fmaxf(m, __shfl_xor_sync(0xffffffffu, m, o));
        float ssum = 0.f;
        for (int j = l16; j < 512; j += 16) {
            float p = __expf(sm[SOFF_S + il*516 + j] - m);
            sm[SOFF_S + il*516 + j] = p;
            ssum += p;
        }
#pragma unroll
        for (int o = 8; o >= 1; o >>= 1) ssum += __shfl_xor_sync(0xffffffffu, ssum, o);
        if (l16 == 0) sm[SOFF_RS + il] = ssum;
    }

    // ---- phase 3: P @ V (warp owns d cols [8w,8w+8)) ----
    float p0=0.f, p1=0.f, p2=0.f, p3=0.f;
    for (int j0 = 0; j0 < QLEN; j0 += 64) {
        __syncthreads();
        {
            const int jl = tid >> 4, d4 = (tid & 15) * 4;
#pragma unroll
            for (int p = 0; p < 4; p++) {
                int j = jl + p*16;
                float4 vv = *(const float4*)&g_v[((size_t)(j0+j)*BSZ + b)*DM + n*DH + d4];
                *(uint4*)&smU[SOFF_KR + j*72 + d4] = tf4(vv);   // stride 72 for PV banks
            }
        }
        __syncthreads();
#pragma unroll
        for (int ks = 0; ks < 8; ks++) {
            int sr = SOFF_S + g*516 + j0 + ks*8 + tig;
            unsigned a[4];
            a[0] = f2tf(sm[sr]);            a[1] = f2tf(sm[sr + 8*516]);
            a[2] = f2tf(sm[sr + 4]);        a[3] = f2tf(sm[sr + 8*516 + 4]);
            int vr = SOFF_KR + (ks*8 + tig)*72 + warp*8 + g;
            mma8(p0, p1, p2, p3, a, smU[vr], smU[vr + 4*72]);
        }
    }
    float inv0 = 1.0f / sm[SOFF_RS + g];
    float inv1 = 1.0f / sm[SOFF_RS + g + 8];
    *(float2*)&av[((size_t)(i0+g)*BSZ + b)*DM + n*DH + warp*8 + 2*tig]   = make_float2(p0*inv0, p1*inv0);
    *(float2*)&av[((size_t)(i0+g+8)*BSZ + b)*DM + n*DH + warp*8 + 2*tig] = make_float2(p2*inv1, p3*inv1);
}

// ---------------- residual + LayerNorm --------------------------------------
__global__ __launch_bounds__(256) void ln_kernel(
    const float* __restrict__ resid_h, const float* __restrict__ resid_g,
    const float* __restrict__ gamma, const float* __restrict__ beta,
    float* __restrict__ out)
{
    __shared__ float red[8];
    __shared__ float bval;
    const int row = blockIdx.x;
    const int st  = blockIdx.y;
    const float* proj  = st ? g_og : g_oh;
    const float* resid = st ? resid_g : resid_h;
    float* o = out + (size_t)st * MROWS * DM + (size_t)row * DM;
    const int tid = threadIdx.x;
    const int lane = tid & 31, w = tid >> 5;

    float4 pv = *(const float4*)&proj [(size_t)row*DM + tid*4];
    float4 rv = *(const float4*)&resid[(size_t)row*DM + tid*4];
    float v0 = pv.x+rv.x, v1 = pv.y+rv.y, v2 = pv.z+rv.z, v3 = pv.w+rv.w;

    float s = v0+v1+v2+v3;
#pragma unroll
    for (int off = 16; off >= 1; off >>= 1) s += __shfl_xor_sync(0xffffffffu, s, off);
    if (lane == 0) red[w] = s;
    __syncthreads();
    if (tid == 0) {
        float t = 0.f;
#pragma unroll
        for (int i = 0; i < 8; i++) t += red[i];
        bval = t * (1.0f / DM);
    }
    __syncthreads();
    const float mu = bval;
    float d0 = v0-mu, d1 = v1-mu, d2 = v2-mu, d3 = v3-mu;
    float sq = d0*d0 + d1*d1 + d2*d2 + d3*d3;
#pragma unroll
    for (int off = 16; off >= 1; off >>= 1) sq += __shfl_xor_sync(0xffffffffu, sq, off);
    __syncthreads();
    if (lane == 0) red[w] = sq;
    __syncthreads();
    if (tid == 0) {
        float t = 0.f;
#pragma unroll
        for (int i = 0; i < 8; i++) t += red[i];
        bval = rsqrtf(t * (1.0f / DM) + 1e-12f);
    }
    __syncthreads();
    const float rstd = bval;
    float4 gm = *(const float4*)&gamma[tid*4];
    float4 bt = *(const float4*)&beta[tid*4];
    *(float4*)&o[tid*4] = make_float4(d0*rstd*gm.x + bt.x, d1*rstd*gm.y + bt.y,
                                      d2*rstd*gm.z + bt.z, d3*rstd*gm.w + bt.w);
}

// ---------------- launch ------------------------------------------------------
extern "C" void kernel_launch(void* const* d_in, const int* in_sizes, int n_in,
                              void* d_out, int out_size)
{
    const float* h    = (const float*)d_in[0];
    const float* g    = (const float*)d_in[1];
    const float* r    = (const float*)d_in[2];
    const float* amh  = (const float*)d_in[3];
    const float* amg  = (const float*)d_in[4];
    const float* seg  = (const float*)d_in[5];
    const float* wq   = (const float*)d_in[6];
    const float* wk   = (const float*)d_in[7];
    const float* wv   = (const float*)d_in[8];
    const float* wo   = (const float*)d_in[9];
    const float* wr   = (const float*)d_in[10];
    const float* rwb  = (const float*)d_in[11];
    const float* rrb  = (const float*)d_in[12];
    const float* rsb  = (const float*)d_in[13];
    const float* se   = (const float*)d_in[14];
    const float* gam  = (const float*)d_in[15];
    const float* bet  = (const float*)d_in[16];
    float* out = (float*)d_out;

    float *qh, *qg, *k, *v, *kr, *avh, *avg, *oh, *og;
    cudaGetSymbolAddress((void**)&qh,  g_qh);
    cudaGetSymbolAddress((void**)&qg,  g_qg);
    cudaGetSymbolAddress((void**)&k,   g_k);
    cudaGetSymbolAddress((void**)&v,   g_v);
    cudaGetSymbolAddress((void**)&kr,  g_kr);
    cudaGetSymbolAddress((void**)&avh, g_avh);
    cudaGetSymbolAddress((void**)&avg, g_avg);
    cudaGetSymbolAddress((void**)&oh,  g_oh);
    cudaGetSymbolAddress((void**)&og,  g_og);

    cudaFuncSetAttribute(attn_tc_kernel,
                         cudaFuncAttributeMaxDynamicSharedMemorySize, ATTN_BYTES);

    dim3 blk(256);
    // projections (tf32)
    gemm_nn_tf32<<<dim3(8, 32), blk>>>(h, wq, qh);
    gemm_nn_tf32<<<dim3(8, 32), blk>>>(g, wq, qg);
    gemm_nn_tf32<<<dim3(8, 32), blk>>>(h, wk, k);
    gemm_nn_tf32<<<dim3(8, 32), blk>>>(h, wv, v);
    gemm_nn_tf32<<<dim3(8, 64), blk>>>(r, wr, kr);
    // fused relative attention (both streams), tensor cores
    attn_tc_kernel<<<dim3(QLEN/16, BSZ*NH, 2), blk, ATTN_BYTES>>>(
        amh, amg, seg, rwb, rrb, rsb, se);
    // output projection (W^T contraction, tf32)
    gemm_tn_tf32<<<dim3(8, 32), blk>>>(avh, wo, oh);
    gemm_tn_tf32<<<dim3(8, 32), blk>>>(avg, wo, og);
    // residual + layernorm
    ln_kernel<<<dim3(MROWS, 2), blk>>>(h, g, gam, bet, out);
}

// round 4
// speedup vs baseline: 3.5197x; 1.2352x over previous
#include <cuda_runtime.h>
#include <cstdint>

#define QLEN 512
#define BSZ 8
#define NH 16
#define DH 64
#define DM 1024
#define MROWS (QLEN*BSZ)   /* 4096 */
#define RROWS (1024*BSZ)   /* 8192 */

// ---------------- scratch (device globals) ----------------------------------
__device__ float g_qh [MROWS*DM];
__device__ float g_qg [MROWS*DM];
__device__ float g_k  [MROWS*DM];
__device__ float g_v  [MROWS*DM];
__device__ float g_kr [RROWS*DM];
__device__ float g_avh[MROWS*DM];
__device__ float g_avg[MROWS*DM];
__device__ float g_oh [MROWS*DM];
__device__ float g_og [MROWS*DM];
// packed bits: mask [st][b*16+n][i][j/32], seg-diff [b][i][j/32]
__device__ unsigned g_mbits[2u*BSZ*NH*QLEN*16];
__device__ unsigned g_sbits[BSZ*QLEN*16];

// ---------------- tf32 helpers ----------------------------------------------
__device__ __forceinline__ unsigned f2tf(float x) {
    unsigned r;
    asm("cvt.rna.tf32.f32 %0, %1;" : "=r"(r) : "f"(x));
    return r;
}
__device__ __forceinline__ void mma8(float &c0, float &c1, float &c2, float &c3,
                                     const unsigned a[4], unsigned b0, unsigned b1)
{
    asm volatile("mma.sync.aligned.m16n8k8.row.col.f32.tf32.tf32.f32 "
        "{%0,%1,%2,%3},{%4,%5,%6,%7},{%8,%9},{%0,%1,%2,%3};"
        : "+f"(c0), "+f"(c1), "+f"(c2), "+f"(c3)
        : "r"(a[0]), "r"(a[1]), "r"(a[2]), "r"(a[3]), "r"(b0), "r"(b1));
}
__device__ __forceinline__ uint4 tf4(float4 v, float4 w) {
    return make_uint4(f2tf(v.x + w.x), f2tf(v.y + w.y), f2tf(v.z + w.z), f2tf(v.w + w.w));
}
__device__ __forceinline__ uint4 tf4s(float4 v, float4 w) {   // scaled by 1/8 (exact)
    return make_uint4(f2tf(0.125f*(v.x + w.x)), f2tf(0.125f*(v.y + w.y)),
                      f2tf(0.125f*(v.z + w.z)), f2tf(0.125f*(v.w + w.w)));
}
__device__ __forceinline__ uint4 tf4(float4 v) {
    return make_uint4(f2tf(v.x), f2tf(v.y), f2tf(v.z), f2tf(v.w));
}

// ---------------- bit-pack masks + seg ---------------------------------------
__global__ __launch_bounds__(256) void pack_bits_kernel(
    const float* __restrict__ mh, const float* __restrict__ mg,
    const float* __restrict__ seg)
{
    const int gw = (blockIdx.x * 256 + threadIdx.x) >> 5;
    const int lane = threadIdx.x & 31;
    if (gw < 2*BSZ*NH*QLEN/ (QLEN) * QLEN) {} // (no-op; clarity below)
    if (gw < 131072) {                       // mask warps: [st][bn][i]
        const int st = gw >> 16;
        const int rem = gw & 65535;
        const int bn = rem >> 9;             // b*16+n
        const int i  = rem & 511;
        const int b = bn >> 4, n = bn & 15;
        const float* m = st ? mg : mh;
        const unsigned obase = (unsigned)(st*BSZ*NH*QLEN + bn*QLEN + i)*16;
#pragma unroll
        for (int w = 0; w < 16; w++) {
            const int j = w*32 + lane;
            float v = m[((size_t)i*QLEN + j)*(BSZ*NH) + b*NH + n];
            unsigned bits = __ballot_sync(0xffffffffu, v > 0.5f);
            if (lane == 0) g_mbits[obase + w] = bits;
        }
    } else if (gw < 131072 + 4096) {         // seg warps: [b][i]
        const int rem = gw - 131072;
        const int b = rem >> 9, i = rem & 511;
#pragma unroll
        for (int w = 0; w < 16; w++) {
            const int j = w*32 + lane;
            float v = seg[(((size_t)i*QLEN + j)*BSZ + b)*2 + 1];  // diff indicator
            unsigned bits = __ballot_sync(0xffffffffu, v > 0.5f);
            if (lane == 0) g_sbits[(b*QLEN + i)*16 + w] = bits;
        }
    }
}

// ---------------- TF32 GEMM nn (merged: all 5 projections) -------------------
__global__ __launch_bounds__(256) void gemm_nn_all(
    const float* __restrict__ h, const float* __restrict__ gq,
    const float* __restrict__ r,
    const float* __restrict__ wq, const float* __restrict__ wk,
    const float* __restrict__ wv, const float* __restrict__ wr)
{
    __shared__ unsigned As[128*36];
    __shared__ unsigned Bs[32*136];
    const int bid = blockIdx.x;
    const float *A, *W; float *C; int tile;
    if (bid < 1024) {
        const int which = bid >> 8; tile = bid & 255;
        A = (which == 1) ? gq : h;
        W = (which <= 1) ? wq : (which == 2 ? wk : wv);
        C = (which == 0) ? g_qh : (which == 1) ? g_qg : (which == 2) ? g_k : g_v;
    } else { A = r; W = wr; C = g_kr; tile = bid - 1024; }
    const int m0 = (tile >> 3) * 128, n0 = (tile & 7) * 128;

    const int tid = threadIdx.x;
    const int lane = tid & 31, warp = tid >> 5;
    const int g = lane >> 2, tig = lane & 3;
    const int wm = (warp >> 2) * 64, wn = (warp & 3) * 32;

    float acc[4][4][4];
#pragma unroll
    for (int mt = 0; mt < 4; mt++)
#pragma unroll
        for (int nt = 0; nt < 4; nt++)
#pragma unroll
            for (int i = 0; i < 4; i++) acc[mt][nt][i] = 0.f;

    const int ar = tid >> 3, ac4 = (tid & 7) * 4;
    const int br = tid >> 5, bc4 = (tid & 31) * 4;

    for (int k0 = 0; k0 < DM; k0 += 32) {
#pragma unroll
        for (int p = 0; p < 4; p++) {
            float4 v = *(const float4*)&A[(size_t)(m0 + ar + p*32)*DM + k0 + ac4];
            *(uint4*)&As[(ar + p*32)*36 + ac4] = tf4(v);
        }
#pragma unroll
        for (int p = 0; p < 4; p++) {
            float4 v = *(const float4*)&W[(size_t)(k0 + br + p*8)*DM + n0 + bc4];
            *(uint4*)&Bs[(br + p*8)*136 + bc4] = tf4(v);
        }
        __syncthreads();
#pragma unroll
        for (int ks = 0; ks < 4; ks++) {
            unsigned af[4][4], bf[4][2];
#pragma unroll
            for (int mt = 0; mt < 4; mt++) {
                int rr = (wm + mt*16 + g)*36 + ks*8 + tig;
                af[mt][0] = As[rr];      af[mt][1] = As[rr + 8*36];
                af[mt][2] = As[rr + 4];  af[mt][3] = As[rr + 8*36 + 4];
            }
#pragma unroll
            for (int nt = 0; nt < 4; nt++) {
                int rr = (ks*8 + tig)*136 + wn + nt*8 + g;
                bf[nt][0] = Bs[rr];  bf[nt][1] = Bs[rr + 4*136];
            }
#pragma unroll
            for (int mt = 0; mt < 4; mt++)
#pragma unroll
                for (int nt = 0; nt < 4; nt++)
                    mma8(acc[mt][nt][0], acc[mt][nt][1], acc[mt][nt][2], acc[mt][nt][3],
                         af[mt], bf[nt][0], bf[nt][1]);
        }
        __syncthreads();
    }
#pragma unroll
    for (int mt = 0; mt < 4; mt++) {
        int row = m0 + wm + mt*16 + g;
#pragma unroll
        for (int nt = 0; nt < 4; nt++) {
            int col = n0 + wn + nt*8 + 2*tig;
            *(float2*)&C[(size_t)row*DM + col]     = make_float2(acc[mt][nt][0], acc[mt][nt][1]);
            *(float2*)&C[(size_t)(row+8)*DM + col] = make_float2(acc[mt][nt][2], acc[mt][nt][3]);
        }
    }
}

// ---------------- TF32 GEMM tn (merged: both output projections) -------------
__global__ __launch_bounds__(256) void gemm_tn_all(const float* __restrict__ wo)
{
    __shared__ unsigned As[128*36];
    __shared__ unsigned Bs[128*36];
    const int bid = blockIdx.x;
    const float* A = (bid < 256) ? g_avh : g_avg;
    float*       C = (bid < 256) ? g_oh  : g_og;
    const int tile = bid & 255;
    const int m0 = (tile >> 3) * 128, n0 = (tile & 7) * 128;

    const int tid = threadIdx.x;
    const int lane = tid & 31, warp = tid >> 5;
    const int g = lane >> 2, tig = lane & 3;
    const int wm = (warp >> 2) * 64, wn = (warp & 3) * 32;

    float acc[4][4][4];
#pragma unroll
    for (int mt = 0; mt < 4; mt++)
#pragma unroll
        for (int nt = 0; nt < 4; nt++)
#pragma unroll
            for (int i = 0; i < 4; i++) acc[mt][nt][i] = 0.f;

    const int ar = tid >> 3, ac4 = (tid & 7) * 4;

    for (int k0 = 0; k0 < DM; k0 += 32) {
#pragma unroll
        for (int p = 0; p < 4; p++) {
            float4 v = *(const float4*)&A[(size_t)(m0 + ar + p*32)*DM + k0 + ac4];
            *(uint4*)&As[(ar + p*32)*36 + ac4] = tf4(v);
            float4 w = *(const float4*)&wo[(size_t)(n0 + ar + p*32)*DM + k0 + ac4];
            *(uint4*)&Bs[(ar + p*32)*36 + ac4] = tf4(w);
        }
        __syncthreads();
#pragma unroll
        for (int ks = 0; ks < 4; ks++) {
            unsigned af[4][4], bf[4][2];
#pragma unroll
            for (int mt = 0; mt < 4; mt++) {
                int rr = (wm + mt*16 + g)*36 + ks*8 + tig;
                af[mt][0] = As[rr];      af[mt][1] = As[rr + 8*36];
                af[mt][2] = As[rr + 4];  af[mt][3] = As[rr + 8*36 + 4];
            }
#pragma unroll
            for (int nt = 0; nt < 4; nt++) {
                int rr = (wn + nt*8 + g)*36 + ks*8 + tig;
                bf[nt][0] = Bs[rr];  bf[nt][1] = Bs[rr + 4];
            }
#pragma unroll
            for (int mt = 0; mt < 4; mt++)
#pragma unroll
                for (int nt = 0; nt < 4; nt++)
                    mma8(acc[mt][nt][0], acc[mt][nt][1], acc[mt][nt][2], acc[mt][nt][3],
                         af[mt], bf[nt][0], bf[nt][1]);
        }
        __syncthreads();
    }
#pragma unroll
    for (int mt = 0; mt < 4; mt++) {
        int row = m0 + wm + mt*16 + g;
#pragma unroll
        for (int nt = 0; nt < 4; nt++) {
            int col = n0 + wn + nt*8 + 2*tig;
            *(float2*)&C[(size_t)row*DM + col]     = make_float2(acc[mt][nt][0], acc[mt][nt][1]);
            *(float2*)&C[(size_t)(row+8)*DM + col] = make_float2(acc[mt][nt][2], acc[mt][nt][3]);
        }
    }
}

// ---------------- fused tensor-core attention --------------------------------
#define SOFF_S   0                  // scores 16 x 512, row stride 516
#define SOFF_SAC 8256               // ac chunk 16 x 64, stride 68
#define SOFF_W   9344               // bd window 16 x 80, stride 84
#define SOFF_EF  10688              // 16 x 2
#define SOFF_RS  10720              // 16 rowsums
#define SOFF_K   10736              // K chunk 64 x 64 (stride 68); Q staging (2 x 16 x 68)
#define SOFF_KR  15088              // kr window 80 x 64 (stride 68); V chunk 64 x 64 (stride 72)
#define ATTN_WORDS 20528
#define ATTN_BYTES (ATTN_WORDS*4)

__global__ __launch_bounds__(256) void attn_tc_kernel(
    const float* __restrict__ rwb, const float* __restrict__ rrb,
    const float* __restrict__ rsb, const float* __restrict__ se)
{
    extern __shared__ float sm[];
    unsigned* smU = (unsigned*)sm;
    const int tid  = threadIdx.x;
    const int lane = tid & 31, warp = tid >> 5;
    const int g = lane >> 2, tig = lane & 3;
    const int i0 = blockIdx.x * 16;
    const int b  = blockIdx.y >> 4;
    const int n  = blockIdx.y & 15;
    const int st = blockIdx.z;

    const float* q  = st ? g_qg : g_qh;
    float*       av = st ? g_avg : g_avh;
    const unsigned* mbits = &g_mbits[(size_t)(st*BSZ*NH + blockIdx.y)*QLEN*16];
    const unsigned* sbits = &g_sbits[b*QLEN*16];

    // ---- stage (q+rw)/8, (q+rr)/8 as tf32 (scale folded; exact pow2) ----
    {
        const int il = tid >> 4, d4 = (tid & 15) * 4;
        float4 qv = *(const float4*)&q[((size_t)(i0+il)*BSZ + b)*DM + n*DH + d4];
        float4 rw = *(const float4*)&rwb[n*DH + d4];
        float4 rr = *(const float4*)&rrb[n*DH + d4];
        *(uint4*)&smU[SOFF_K + il*68 + d4]        = tf4s(qv, rw);
        *(uint4*)&smU[SOFF_K + 1088 + il*68 + d4] = tf4s(qv, rr);
    }
    // ef[i][s] = dot(q[i]+r_s_bias, seg_embed[s,n,:]) / 8  (fp32)
    if (tid < 32) {
        const int il = tid >> 1, s = tid & 1;
        const float* qrow = &q[((size_t)(i0+il)*BSZ + b)*DM + n*DH];
        const float* srow = &se[(s*NH + n)*DH];
        const float* rs   = &rsb[n*DH];
        float acc = 0.f;
#pragma unroll 8
        for (int d = 0; d < DH; d++) acc += (qrow[d] + rs[d]) * srow[d];
        sm[SOFF_EF + il*2 + s] = acc * 0.125f;
    }
    __syncthreads();

    // ---- hoist Q fragments ----
    unsigned qa[8][4], qb[8][4];
#pragma unroll
    for (int ks = 0; ks < 8; ks++) {
        int r = SOFF_K + g*68 + ks*8 + tig;
        qa[ks][0] = smU[r];       qa[ks][1] = smU[r + 8*68];
        qa[ks][2] = smU[r + 4];   qa[ks][3] = smU[r + 8*68 + 4];
        r += 1088;
        qb[ks][0] = smU[r];       qb[ks][1] = smU[r + 8*68];
        qb[ks][2] = smU[r + 4];   qb[ks][3] = smU[r + 8*68 + 4];
    }

    // ---- phase 1: scores ----
    for (int j0 = 0; j0 < QLEN; j0 += 64) {
        __syncthreads();
        {
            const int jl = tid >> 4, d4 = (tid & 15) * 4;
#pragma unroll
            for (int p = 0; p < 4; p++) {
                int j = jl + p*16;
                float4 kv = *(const float4*)&g_k[((size_t)(j0+j)*BSZ + b)*DM + n*DH + d4];
                *(uint4*)&smU[SOFF_K + j*68 + d4] = tf4(kv);
            }
            const int base = 512 + j0 - i0 - 15;
#pragma unroll
            for (int p = 0; p < 5; p++) {
                int w = jl + p*16;
                int r = base + w; if (r > 1023) r = 1023;   // row 79 unused
                float4 kv = *(const float4*)&g_kr[((size_t)r*BSZ + b)*DM + n*DH + d4];
                *(uint4*)&smU[SOFF_KR + w*68 + d4] = tf4(kv);
            }
        }
        __syncthreads();
        // ac tile
        {
            float c0=0.f, c1=0.f, c2=0.f, c3=0.f;
#pragma unroll
            for (int ks = 0; ks < 8; ks++) {
                int r = SOFF_K + (warp*8 + g)*68 + ks*8 + tig;
                mma8(c0, c1, c2, c3, qa[ks], smU[r], smU[r + 4]);
            }
            *(float2*)&sm[SOFF_SAC + g*68 + warp*8 + 2*tig]       = make_float2(c0, c1);
            *(float2*)&sm[SOFF_SAC + (g+8)*68 + warp*8 + 2*tig]   = make_float2(c2, c3);
        }
        // bd window tiles
        for (int bt = warp; bt < 10; bt += 8) {
            float c0=0.f, c1=0.f, c2=0.f, c3=0.f;
#pragma unroll
            for (int ks = 0; ks < 8; ks++) {
                int r = SOFF_KR + (bt*8 + g)*68 + ks*8 + tig;
                mma8(c0, c1, c2, c3, qb[ks], smU[r], smU[r + 4]);
            }
            *(float2*)&sm[SOFF_W + g*84 + bt*8 + 2*tig]     = make_float2(c0, c1);
            *(float2*)&sm[SOFF_W + (g+8)*84 + bt*8 + 2*tig] = make_float2(c2, c3);
        }
        __syncthreads();
        // assemble: S = ac + bd_shift + ef_sel ; masked -> -1e30 (exact, absorption)
        {
            const int il = tid >> 4, jj0 = (tid & 15) * 4;
            const int widx = (i0+il)*16 + ((j0 + jj0) >> 5);
            const unsigned mw = mbits[widx];
            const unsigned sw = sbits[widx];
            const int bit0 = jj0 & 31;
            const float e0 = sm[SOFF_EF + il*2], e1 = sm[SOFF_EF + il*2 + 1];
#pragma unroll
            for (int u = 0; u < 4; u++) {
                const int jj = jj0 + u;
                const int bit = bit0 + u;
                float v = sm[SOFF_SAC + il*68 + jj] + sm[SOFF_W + il*84 + jj + 15 - il];
                v += ((sw >> bit) & 1u) ? e1 : e0;
                if ((mw >> bit) & 1u) v = -1e30f;
                sm[SOFF_S + il*516 + j0 + jj] = v;
            }
        }
    }
    __syncthreads();

    // ---- phase 2: softmax ----
    {
        const int il  = warp*2 + (lane >> 4);
        const int l16 = lane & 15;
        float m = -3.0e38f;
        for (int j = l16; j < 512; j += 16) m = fmaxf(m, sm[SOFF_S + il*516 + j]);
#pragma unroll
        for (int o = 8; o >= 1; o >>= 1) m = fmaxf(m, __shfl_xor_sync(0xffffffffu, m, o));
        float ssum = 0.f;
        for (int j = l16; j < 512; j += 16) {
            float p = __expf(sm[SOFF_S + il*516 + j] - m);
            sm[SOFF_S + il*516 + j] = p;
            ssum += p;
        }
#pragma unroll
        for (int o = 8; o >= 1; o >>= 1) ssum += __shfl_xor_sync(0xffffffffu, ssum, o);
        if (l16 == 0) sm[SOFF_RS + il] = ssum;
    }

    // ---- phase 3: P @ V ----
    float p0=0.f, p1=0.f, p2=0.f, p3=0.f;
    for (int j0 = 0; j0 < QLEN; j0 += 64) {
        __syncthreads();
        {
            const int jl = tid >> 4, d4 = (tid & 15) * 4;
#pragma unroll
            for (int p = 0; p < 4; p++) {
                int j = jl + p*16;
                float4 vv = *(const float4*)&g_v[((size_t)(j0+j)*BSZ + b)*DM + n*DH + d4];
                *(uint4*)&smU[SOFF_KR + j*72 + d4] = tf4(vv);
            }
        }
        __syncthreads();
#pragma unroll
        for (int ks = 0; ks < 8; ks++) {
            int sr = SOFF_S + g*516 + j0 + ks*8 + tig;
            unsigned a[4];
            a[0] = f2tf(sm[sr]);            a[1] = f2tf(sm[sr + 8*516]);
            a[2] = f2tf(sm[sr + 4]);        a[3] = f2tf(sm[sr + 8*516 + 4]);
            int vr = SOFF_KR + (ks*8 + tig)*72 + warp*8 + g;
            mma8(p0, p1, p2, p3, a, smU[vr], smU[vr + 4*72]);
        }
    }
    float inv0 = 1.0f / sm[SOFF_RS + g];
    float inv1 = 1.0f / sm[SOFF_RS + g + 8];
    *(float2*)&av[((size_t)(i0+g)*BSZ + b)*DM + n*DH + warp*8 + 2*tig]   = make_float2(p0*inv0, p1*inv0);
    *(float2*)&av[((size_t)(i0+g+8)*BSZ + b)*DM + n*DH + warp*8 + 2*tig] = make_float2(p2*inv1, p3*inv1);
}

// ---------------- residual + LayerNorm --------------------------------------
__global__ __launch_bounds__(256) void ln_kernel(
    const float* __restrict__ resid_h, const float* __restrict__ resid_g,
    const float* __restrict__ gamma, const float* __restrict__ beta,
    float* __restrict__ out)
{
    __shared__ float red[8];
    __shared__ float bval;
    const int row = blockIdx.x;
    const int st  = blockIdx.y;
    const float* proj  = st ? g_og : g_oh;
    const float* resid = st ? resid_g : resid_h;
    float* o = out + (size_t)st * MROWS * DM + (size_t)row * DM;
    const int tid = threadIdx.x;
    const int lane = tid & 31, w = tid >> 5;

    float4 pv = *(const float4*)&proj [(size_t)row*DM + tid*4];
    float4 rv = *(const float4*)&resid[(size_t)row*DM + tid*4];
    float v0 = pv.x+rv.x, v1 = pv.y+rv.y, v2 = pv.z+rv.z, v3 = pv.w+rv.w;

    float s = v0+v1+v2+v3;
#pragma unroll
    for (int off = 16; off >= 1; off >>= 1) s += __shfl_xor_sync(0xffffffffu, s, off);
    if (lane == 0) red[w] = s;
    __syncthreads();
    if (tid == 0) {
        float t = 0.f;
#pragma unroll
        for (int i = 0; i < 8; i++) t += red[i];
        bval = t * (1.0f / DM);
    }
    __syncthreads();
    const float mu = bval;
    float d0 = v0-mu, d1 = v1-mu, d2 = v2-mu, d3 = v3-mu;
    float sq = d0*d0 + d1*d1 + d2*d2 + d3*d3;
#pragma unroll
    for (int off = 16; off >= 1; off >>= 1) sq += __shfl_xor_sync(0xffffffffu, sq, off);
    __syncthreads();
    if (lane == 0) red[w] = sq;
    __syncthreads();
    if (tid == 0) {
        float t = 0.f;
#pragma unroll
        for (int i = 0; i < 8; i++) t += red[i];
        bval = rsqrtf(t * (1.0f / DM) + 1e-12f);
    }
    __syncthreads();
    const float rstd = bval;
    float4 gm = *(const float4*)&gamma[tid*4];
    float4 bt = *(const float4*)&beta[tid*4];
    *(float4*)&o[tid*4] = make_float4(d0*rstd*gm.x + bt.x, d1*rstd*gm.y + bt.y,
                                      d2*rstd*gm.z + bt.z, d3*rstd*gm.w + bt.w);
}

// ---------------- launch ------------------------------------------------------
extern "C" void kernel_launch(void* const* d_in, const int* in_sizes, int n_in,
                              void* d_out, int out_size)
{
    const float* h    = (const float*)d_in[0];
    const float* g    = (const float*)d_in[1];
    const float* r    = (const float*)d_in[2];
    const float* amh  = (const float*)d_in[3];
    const float* amg  = (const float*)d_in[4];
    const float* seg  = (const float*)d_in[5];
    const float* wq   = (const float*)d_in[6];
    const float* wk   = (const float*)d_in[7];
    const float* wv   = (const float*)d_in[8];
    const float* wo   = (const float*)d_in[9];
    const float* wr   = (const float*)d_in[10];
    const float* rwb  = (const float*)d_in[11];
    const float* rrb  = (const float*)d_in[12];
    const float* rsb  = (const float*)d_in[13];
    const float* se   = (const float*)d_in[14];
    const float* gam  = (const float*)d_in[15];
    const float* bet  = (const float*)d_in[16];
    float* out = (float*)d_out;

    cudaFuncSetAttribute(attn_tc_kernel,
                         cudaFuncAttributeMaxDynamicSharedMemorySize, ATTN_BYTES);

    dim3 blk(256);
    // bit-pack masks + seg (independent of projections)
    pack_bits_kernel<<<16896, blk>>>(amh, amg, seg);
    // all 5 projections in one launch
    gemm_nn_all<<<1536, blk>>>(h, g, r, wq, wk, wv, wr);
    // fused relative attention (both streams)
    attn_tc_kernel<<<dim3(QLEN/16, BSZ*NH, 2), blk, ATTN_BYTES>>>(rwb, rrb, rsb, se);
    // both output projections in one launch
    gemm_tn_all<<<512, blk>>>(wo);
    // residual + layernorm
    ln_kernel<<<dim3(MROWS, 2), blk>>>(h, g, gam, bet, out);
}